// round 7
// baseline (speedup 1.0000x reference)
#include <cuda_runtime.h>

#define DD 8
#define BX 32            // m-pairs per block (tx) -> 64 m columns
#define BY 8             // ty; each thread does rows ty and ty+8 -> 16 n rows

typedef unsigned long long u64;

// constant layout: [0..63] w | [64..191] ks (per j: 8x KMm, 8x -Km) | [192..223] pl (per j: lj2,alpha,beta,gamma) | [224] sig0
#define C_W   0
#define C_KS  64
#define C_PL  192
#define C_S0  224
#define C_TOT 232

__constant__ __align__(16) u64 cC[C_TOT];
__device__   __align__(16) u64 gScratch[C_TOT];

// packed f32x2 ops (Blackwell sm_103a)
#define FMA2(d,a,b,c) asm("fma.rn.f32x2 %0, %1, %2, %3;" : "=l"(d) : "l"(a), "l"(b), "l"(c))
#define MUL2(d,a,b)   asm("mul.rn.f32x2 %0, %1, %2;"     : "=l"(d) : "l"(a), "l"(b))
#define ADD2(d,a,b)   asm("add.rn.f32x2 %0, %1, %2;"     : "=l"(d) : "l"(a), "l"(b))

__device__ __forceinline__ u64 pack2(float lo, float hi) {
    u64 r; asm("mov.b64 %0, {%1, %2};" : "=l"(r) : "f"(lo), "f"(hi)); return r;
}
__device__ __forceinline__ void unpack2(u64 v, float& lo, float& hi) {
    asm("mov.b64 {%0, %1}, %2;" : "=f"(lo), "=f"(hi) : "l"(v));
}
__device__ __forceinline__ float ex2a(float x) {
    float r; asm("ex2.approx.f32 %0, %1;" : "=f"(r) : "f"(x)); return r;
}
__device__ __forceinline__ u64 dup(float v) {
    unsigned u = __float_as_uint(v);
    return ((u64)u << 32) | (u64)u;
}

// ---------- setup kernel: derive constants once ----------
__global__ void setup_kernel(const float* __restrict__ L, const float* __restrict__ sig)
{
    int tid = threadIdx.x;            // 0..63
    int c = tid >> 3, j = tid & 7;
    float Ljc = L[j * DD + c];
    float inv2_jc = 1.0f / (Ljc * Ljc);
    float L0c = L[c];
    float inv2_0c = 1.0f / (L0c * L0c);
    float Mcj = inv2_0c + inv2_jc;
    float L0j = L[j];
    float lj2 = L0j * L0j;
    float Kcj = sig[j] / (lj2 * lj2) * Mcj * Mcj;
    gScratch[C_KS + j * 16 + c]     = dup(Kcj / Mcj);
    gScratch[C_KS + j * 16 + 8 + c] = dup(-Kcj);
    float Lak = L[c * DD + j];
    gScratch[C_W + c * DD + j] = dup(-0.5f * 1.44269504088896340736f / (Lak * Lak));
    if (c == j) {
        int l = c;
        float tl = Mcj;                       // M[l][l]
        float c1 = 5.0f * tl + lj2 * tl * tl;
        float c2 = tl * tl;
        float c3 = 2.0f + lj2 * tl;
        float F  = sig[l] / (lj2 * lj2);
        float Kd = Kcj;
        float Md = 1.0f / tl;
        gScratch[C_PL + l * 4 + 0] = dup(lj2);
        gScratch[C_PL + l * 4 + 1] = dup(F * c3 - Kd * Md * lj2);    // alpha
        gScratch[C_PL + l * 4 + 2] = dup(-F * c1 + Kd * (Md + lj2)); // beta
        gScratch[C_PL + l * 4 + 3] = dup(F * c2 - Kd);               // gamma
    }
    if (tid == 0) gScratch[C_S0] = dup(sig[0]);
}

// ---------- main kernel ----------
// out[n,m] = sigma0 * E0 * S_total
//   d_k = (x1[n,k]-x2[m,k])^2 ; E_a = exp2( sum_k d_k * w[a,k] )
//   S_total = sum_j [ sum_c (KMm[c,j] - Km[c,j] d_c) E_c ] * E_j * (lj2_j - d_j)
//           + sum_j (alpha_j + beta_j d_j + gamma_j d_j^2) * E_j^2

__global__ __launch_bounds__(256, 3) void taylor_rbf_kernel(
    const float* __restrict__ x1, const float* __restrict__ x2,
    float* __restrict__ out, int N, int M)
{
    __shared__ __align__(16) u64 x1d[16 * DD];   // dup(x1[n0+r][k]), r=0..15
    __shared__ __align__(16) u64 nx2[DD * BX];   // (-x2[m0+2p][k], -x2[m0+2p+1][k])

    const int tx = threadIdx.x;          // 0..31
    const int ty = threadIdx.y;          // 0..7
    const int tid = ty * BX + tx;

    // ---- stage x tiles ----
    const int n0 = blockIdx.y * 16, m0 = blockIdx.x * (2 * BX);
    {   // nx2: 256 entries, one per thread
        int k = tid >> 5, p = tid & 31;
        int mm = m0 + 2 * p;
        float a = (mm     < M) ? x2[mm * DD + k]       : 0.0f;
        float b = (mm + 1 < M) ? x2[(mm + 1) * DD + k] : 0.0f;
        nx2[k * BX + p] = pack2(-a, -b);
    }
    if (tid < 128) {  // x1d: 128 entries
        int r = tid >> 3, k = tid & 7;
        int nn = n0 + r;
        x1d[r * DD + k] = dup((nn < N) ? x1[nn * DD + k] : 0.0f);
    }
    __syncthreads();

    const int n = n0 + ty;           // pair A row
    const int n2 = n + 8;            // pair B row
    const int m = m0 + 2 * tx;
    if (m >= M) return;

    const u64 negone = dup(-1.0f);

    // ---- d for both rows ----
    u64 dA[DD], dB[DD];
#pragma unroll
    for (int k = 0; k < DD; k++) {
        u64 xv = nx2[k * BX + tx];
        u64 fa; ADD2(fa, x1d[ty * DD + k], xv);        MUL2(dA[k], fa, fa);
        u64 fb; ADD2(fb, x1d[(ty + 8) * DD + k], xv);  MUL2(dB[k], fb, fb);
    }

    // ---- E for both rows (weights from const bank) ----
    u64 EA[DD], EB[DD];
#pragma unroll
    for (int a = 0; a < DD; a++) {
        const u64* wr = &cC[C_W + a * DD];
        u64 sA, sB;
        MUL2(sA, dA[0], wr[0]);           MUL2(sB, dB[0], wr[0]);
        FMA2(sA, dA[1], wr[1], sA);       FMA2(sB, dB[1], wr[1], sB);
        FMA2(sA, dA[2], wr[2], sA);       FMA2(sB, dB[2], wr[2], sB);
        FMA2(sA, dA[3], wr[3], sA);       FMA2(sB, dB[3], wr[3], sB);
        FMA2(sA, dA[4], wr[4], sA);       FMA2(sB, dB[4], wr[4], sB);
        FMA2(sA, dA[5], wr[5], sA);       FMA2(sB, dB[5], wr[5], sB);
        FMA2(sA, dA[6], wr[6], sA);       FMA2(sB, dB[6], wr[6], sB);
        FMA2(sA, dA[7], wr[7], sA);       FMA2(sB, dB[7], wr[7], sB);
        float lo, hi;
        unpack2(sA, lo, hi);  EA[a] = pack2(ex2a(lo), ex2a(hi));
        unpack2(sB, lo, hi);  EB[a] = pack2(ex2a(lo), ex2a(hi));
    }

    // ---- merged S + corr loop over j ----
    u64 SA = dup(0.0f), SB = dup(0.0f);
#pragma unroll
    for (int j = 0; j < DD; j++) {
        const u64* kmm = &cC[C_KS + j * 16];       // 8x KMm
        const u64* nkm = &cC[C_KS + j * 16 + 8];   // 8x -Km
        const u64* pl  = &cC[C_PL + j * 4];        // lj2, alpha, beta, gamma

        u64 accA, accB, wp;
        // pair A matvec: acc += (KMm_c - Km_c * d_c) * E_c
        FMA2(wp, nkm[0], dA[0], kmm[0]);  MUL2(accA, wp, EA[0]);
        FMA2(wp, nkm[1], dA[1], kmm[1]);  FMA2(accA, wp, EA[1], accA);
        FMA2(wp, nkm[2], dA[2], kmm[2]);  FMA2(accA, wp, EA[2], accA);
        FMA2(wp, nkm[3], dA[3], kmm[3]);  FMA2(accA, wp, EA[3], accA);
        FMA2(wp, nkm[4], dA[4], kmm[4]);  FMA2(accA, wp, EA[4], accA);
        FMA2(wp, nkm[5], dA[5], kmm[5]);  FMA2(accA, wp, EA[5], accA);
        FMA2(wp, nkm[6], dA[6], kmm[6]);  FMA2(accA, wp, EA[6], accA);
        FMA2(wp, nkm[7], dA[7], kmm[7]);  FMA2(accA, wp, EA[7], accA);
        // pair B matvec
        FMA2(wp, nkm[0], dB[0], kmm[0]);  MUL2(accB, wp, EB[0]);
        FMA2(wp, nkm[1], dB[1], kmm[1]);  FMA2(accB, wp, EB[1], accB);
        FMA2(wp, nkm[2], dB[2], kmm[2]);  FMA2(accB, wp, EB[2], accB);
        FMA2(wp, nkm[3], dB[3], kmm[3]);  FMA2(accB, wp, EB[3], accB);
        FMA2(wp, nkm[4], dB[4], kmm[4]);  FMA2(accB, wp, EB[4], accB);
        FMA2(wp, nkm[5], dB[5], kmm[5]);  FMA2(accB, wp, EB[5], accB);
        FMA2(wp, nkm[6], dB[6], kmm[6]);  FMA2(accB, wp, EB[6], accB);
        FMA2(wp, nkm[7], dB[7], kmm[7]);  FMA2(accB, wp, EB[7], accB);

        // pair A tail: S += acc*E_j*(lj2-d_j) + (alpha + beta d + gamma d^2)*E_j^2
        {
            u64 t;  FMA2(t, dA[j], negone, pl[0]);       // lj2 - d
            u64 et; MUL2(et, EA[j], t);
            FMA2(SA, accA, et, SA);
            u64 E2; MUL2(E2, EA[j], EA[j]);
            u64 u;  FMA2(u, pl[3], dA[j], pl[2]);        // gamma*d + beta
            u64 py; FMA2(py, dA[j], u, pl[1]);           // d*(.) + alpha
            FMA2(SA, py, E2, SA);
        }
        // pair B tail
        {
            u64 t;  FMA2(t, dB[j], negone, pl[0]);
            u64 et; MUL2(et, EB[j], t);
            FMA2(SB, accB, et, SB);
            u64 E2; MUL2(E2, EB[j], EB[j]);
            u64 u;  FMA2(u, pl[3], dB[j], pl[2]);
            u64 py; FMA2(py, dB[j], u, pl[1]);
            FMA2(SB, py, E2, SB);
        }
    }

    // ---- out = sig0 * E0 * S ----
    u64 s0 = cC[C_S0];
    u64 eA; MUL2(eA, EA[0], s0);
    u64 eB; MUL2(eB, EB[0], s0);
    u64 rA; MUL2(rA, SA, eA);
    u64 rB; MUL2(rB, SB, eB);

    bool full = (m + 1 < M);
    if (n < N) {
        long idx = (long)n * M + m;
        if (full) *reinterpret_cast<u64*>(&out[idx]) = rA;
        else { float lo, hi; unpack2(rA, lo, hi); out[idx] = lo; }
    }
    if (n2 < N) {
        long idx = (long)n2 * M + m;
        if (full) *reinterpret_cast<u64*>(&out[idx]) = rB;
        else { float lo, hi; unpack2(rB, lo, hi); out[idx] = lo; }
    }
}

extern "C" void kernel_launch(void* const* d_in, const int* in_sizes, int n_in,
                              void* d_out, int out_size)
{
    const float* x1  = (const float*)d_in[0];
    const float* x2  = (const float*)d_in[1];
    const float* L   = (const float*)d_in[2];
    const float* sig = (const float*)d_in[3];
    float* out = (float*)d_out;

    int N = in_sizes[0] / DD;
    int M = in_sizes[1] / DD;

    setup_kernel<<<1, 64>>>(L, sig);

    void* scratch_addr = nullptr;
    cudaGetSymbolAddress(&scratch_addr, gScratch);
    cudaMemcpyToSymbolAsync(cC, scratch_addr, C_TOT * sizeof(u64), 0,
                            cudaMemcpyDeviceToDevice, 0);

    dim3 block(BX, BY);                                    // 256 threads
    dim3 grid((M + 2 * BX - 1) / (2 * BX), (N + 15) / 16);
    taylor_rbf_kernel<<<grid, block>>>(x1, x2, out, N, M);
}